// round 1
// baseline (speedup 1.0000x reference)
#include <cuda_runtime.h>
#include <math.h>

// ---------------------------------------------------------------------------
// Problem constants: B=8, N=2048, C=1024, heads=2, d=512, H=2048 (mlp hidden)
// M = B*N = 16384 rows.
// ---------------------------------------------------------------------------

#define BM 128
#define BN 128
#define BK 8

enum { EPI_NONE = 0, EPI_BIAS = 1, EPI_BIAS_RES = 2, EPI_BIAS_GELU = 3 };

// Scratch (device globals; allocation-free per harness rules). ~768 MB total.
__device__ float g_xn[16384 * 1024];            // 64 MB  (ln output, reused)
__device__ float g_qkv[16384 * 3072];           // 192 MB
__device__ float g_scores[16ull * 2048 * 2048]; // 256 MB
__device__ float g_attnout[16384 * 1024];       // 64 MB
__device__ float g_x1[16384 * 1024];            // 64 MB  (residual after attn)
__device__ float g_hdn[16384 * 2048];           // 128 MB

// ---------------------------------------------------------------------------
// Generic tiled SGEMM: C[z] = A[z] @ B[z] (+bias)(+resid)(gelu)
// TB=1 -> B is [N,K] row-major and we compute A @ B^T.
// Batch offsets: off = (z/ic)*so + (z%ic)*si  per tensor.
// All of M,N divisible by 128; K divisible by 8; all lds multiples of 4.
// ---------------------------------------------------------------------------
template <int TB, int EPI>
__global__ __launch_bounds__(256) void gemm_k(
    const float* __restrict__ A, const float* __restrict__ B,
    const float* __restrict__ bias, const float* __restrict__ resid,
    float* __restrict__ C,
    int M, int N, int K, int lda, int ldb, int ldc,
    long long soA, long long siA,
    long long soB, long long siB,
    long long soC, long long siC, int ic)
{
    __shared__ float As[BK][BM];
    __shared__ float Bs[BK][BN];

    const int z = blockIdx.z;
    A += (long long)(z / ic) * soA + (long long)(z % ic) * siA;
    B += (long long)(z / ic) * soB + (long long)(z % ic) * siB;
    C += (long long)(z / ic) * soC + (long long)(z % ic) * siC;

    const int m0 = blockIdx.y * BM;
    const int n0 = blockIdx.x * BN;
    const int tid = threadIdx.x;
    const int tx = tid & 15;   // column group (8 cols each)
    const int ty = tid >> 4;   // row group (8 rows each)

    float acc[8][8];
#pragma unroll
    for (int i = 0; i < 8; i++)
#pragma unroll
        for (int j = 0; j < 8; j++) acc[i][j] = 0.0f;

    // A-load mapping: 128 rows x 8 cols, 4 floats/thread
    const int arow = tid >> 1;
    const int acol = (tid & 1) * 4;
    // B-load mapping
    const int brow = TB ? (tid >> 1) : (tid >> 5);
    const int bcol = TB ? ((tid & 1) * 4) : ((tid & 31) * 4);

    for (int k0 = 0; k0 < K; k0 += BK) {
        float4 av = *(const float4*)(A + (size_t)(m0 + arow) * lda + k0 + acol);
        As[acol + 0][arow] = av.x;
        As[acol + 1][arow] = av.y;
        As[acol + 2][arow] = av.z;
        As[acol + 3][arow] = av.w;
        if (TB) {
            float4 bv = *(const float4*)(B + (size_t)(n0 + brow) * ldb + k0 + bcol);
            Bs[bcol + 0][brow] = bv.x;
            Bs[bcol + 1][brow] = bv.y;
            Bs[bcol + 2][brow] = bv.z;
            Bs[bcol + 3][brow] = bv.w;
        } else {
            float4 bv = *(const float4*)(B + (size_t)(k0 + brow) * ldb + n0 + bcol);
            *(float4*)&Bs[brow][bcol] = bv;
        }
        __syncthreads();
#pragma unroll
        for (int kk = 0; kk < BK; kk++) {
            float a[8], b[8];
            *(float4*)(a)     = *(const float4*)&As[kk][ty * 8];
            *(float4*)(a + 4) = *(const float4*)&As[kk][ty * 8 + 4];
            *(float4*)(b)     = *(const float4*)&Bs[kk][tx * 8];
            *(float4*)(b + 4) = *(const float4*)&Bs[kk][tx * 8 + 4];
#pragma unroll
            for (int i = 0; i < 8; i++)
#pragma unroll
                for (int j = 0; j < 8; j++)
                    acc[i][j] = fmaf(a[i], b[j], acc[i][j]);
        }
        __syncthreads();
    }

#pragma unroll
    for (int i = 0; i < 8; i++) {
        const int row = m0 + ty * 8 + i;
#pragma unroll
        for (int j = 0; j < 8; j++) {
            const int col = n0 + tx * 8 + j;
            float v = acc[i][j];
            if (EPI == EPI_BIAS || EPI == EPI_BIAS_RES || EPI == EPI_BIAS_GELU)
                v += bias[col];
            if (EPI == EPI_BIAS_RES)
                v += resid[(size_t)row * ldc + col];
            if (EPI == EPI_BIAS_GELU)
                v = 0.5f * v * (1.0f + erff(v * 0.70710678118654752f));
            C[(size_t)row * ldc + col] = v;
        }
    }
}

// ---------------------------------------------------------------------------
// LayerNorm: one block per row of C=1024
// ---------------------------------------------------------------------------
__global__ __launch_bounds__(256) void ln_k(
    const float* __restrict__ x, const float* __restrict__ w,
    const float* __restrict__ b, float* __restrict__ out, int C)
{
    const size_t row = blockIdx.x;
    const float* xr = x + row * C;
    float sum = 0.0f, sq = 0.0f;
    for (int i = threadIdx.x; i < C; i += blockDim.x) {
        float v = xr[i];
        sum += v;
        sq += v * v;
    }
    __shared__ float s1[32], s2[32];
#pragma unroll
    for (int o = 16; o; o >>= 1) {
        sum += __shfl_xor_sync(0xffffffffu, sum, o);
        sq  += __shfl_xor_sync(0xffffffffu, sq, o);
    }
    const int wid = threadIdx.x >> 5, lid = threadIdx.x & 31;
    if (!lid) { s1[wid] = sum; s2[wid] = sq; }
    __syncthreads();
    if (threadIdx.x < 32) {
        const int nw = blockDim.x >> 5;
        float v1 = (threadIdx.x < nw) ? s1[threadIdx.x] : 0.0f;
        float v2 = (threadIdx.x < nw) ? s2[threadIdx.x] : 0.0f;
#pragma unroll
        for (int o = 16; o; o >>= 1) {
            v1 += __shfl_xor_sync(0xffffffffu, v1, o);
            v2 += __shfl_xor_sync(0xffffffffu, v2, o);
        }
        if (!threadIdx.x) { s1[0] = v1; s2[0] = v2; }
    }
    __syncthreads();
    const float mu = s1[0] / (float)C;
    const float var = s2[0] / (float)C - mu * mu;
    const float rstd = rsqrtf(var + 1e-5f);
    float* orow = out + row * C;
    for (int i = threadIdx.x; i < C; i += blockDim.x)
        orow[i] = (xr[i] - mu) * rstd * w[i] + b[i];
}

// ---------------------------------------------------------------------------
// In-place scaled softmax over rows of length n: softmax(scale * s)
// ---------------------------------------------------------------------------
__global__ __launch_bounds__(256) void softmax_k(float* __restrict__ s, int n, float scale)
{
    float* row = s + (size_t)blockIdx.x * n;
    __shared__ float red[32];
    const int wid = threadIdx.x >> 5, lid = threadIdx.x & 31;
    const int nw = blockDim.x >> 5;

    float mx = -3.4e38f;
    for (int i = threadIdx.x; i < n; i += blockDim.x) mx = fmaxf(mx, row[i]);
#pragma unroll
    for (int o = 16; o; o >>= 1) mx = fmaxf(mx, __shfl_xor_sync(0xffffffffu, mx, o));
    if (!lid) red[wid] = mx;
    __syncthreads();
    if (threadIdx.x < 32) {
        float v = (threadIdx.x < nw) ? red[threadIdx.x] : -3.4e38f;
#pragma unroll
        for (int o = 16; o; o >>= 1) v = fmaxf(v, __shfl_xor_sync(0xffffffffu, v, o));
        if (!threadIdx.x) red[0] = v;
    }
    __syncthreads();
    mx = red[0];
    __syncthreads();  // allow red[] reuse

    float sum = 0.0f;
    for (int i = threadIdx.x; i < n; i += blockDim.x) {
        float e = expf(scale * (row[i] - mx));
        row[i] = e;
        sum += e;
    }
#pragma unroll
    for (int o = 16; o; o >>= 1) sum += __shfl_xor_sync(0xffffffffu, sum, o);
    if (!lid) red[wid] = sum;
    __syncthreads();
    if (threadIdx.x < 32) {
        float v = (threadIdx.x < nw) ? red[threadIdx.x] : 0.0f;
#pragma unroll
        for (int o = 16; o; o >>= 1) v += __shfl_xor_sync(0xffffffffu, v, o);
        if (!threadIdx.x) red[0] = v;
    }
    __syncthreads();
    const float inv = 1.0f / red[0];
    for (int i = threadIdx.x; i < n; i += blockDim.x) row[i] *= inv;
}

// ---------------------------------------------------------------------------
// Launch: 9 kernels, all on the capture stream.
// Inputs (metadata order): x, ln1_w, ln1_b, qkv_w, qkv_b, proj_w, proj_b,
//                          ln2_w, ln2_b, mlp_w1, mlp_b1, mlp_w2, mlp_b2
// ---------------------------------------------------------------------------
extern "C" void kernel_launch(void* const* d_in, const int* in_sizes, int n_in,
                              void* d_out, int out_size)
{
    const float* x      = (const float*)d_in[0];
    const float* ln1_w  = (const float*)d_in[1];
    const float* ln1_b  = (const float*)d_in[2];
    const float* qkv_w  = (const float*)d_in[3];
    const float* qkv_b  = (const float*)d_in[4];
    const float* proj_w = (const float*)d_in[5];
    const float* proj_b = (const float*)d_in[6];
    const float* ln2_w  = (const float*)d_in[7];
    const float* ln2_b  = (const float*)d_in[8];
    const float* mlp_w1 = (const float*)d_in[9];
    const float* mlp_b1 = (const float*)d_in[10];
    const float* mlp_w2 = (const float*)d_in[11];
    const float* mlp_b2 = (const float*)d_in[12];
    float* out = (float*)d_out;

    void *p_xn, *p_qkv, *p_sc, *p_ao, *p_x1, *p_hd;
    cudaGetSymbolAddress(&p_xn,  g_xn);
    cudaGetSymbolAddress(&p_qkv, g_qkv);
    cudaGetSymbolAddress(&p_sc,  g_scores);
    cudaGetSymbolAddress(&p_ao,  g_attnout);
    cudaGetSymbolAddress(&p_x1,  g_x1);
    cudaGetSymbolAddress(&p_hd,  g_hdn);
    float* xn      = (float*)p_xn;
    float* qkv     = (float*)p_qkv;
    float* scores  = (float*)p_sc;
    float* attnout = (float*)p_ao;
    float* x1      = (float*)p_x1;
    float* hdn     = (float*)p_hd;

    const int M = 16384;        // B*N rows
    const long long X = 2048LL * 2048LL;  // per-(b,h) score tile

    // 1. LN1: x -> xn
    ln_k<<<M, 256>>>(x, ln1_w, ln1_b, xn, 1024);

    // 2. QKV GEMM: xn[16384,1024] @ qkv_w[1024,3072] + qkv_b -> qkv
    gemm_k<0, EPI_BIAS><<<dim3(3072 / BN, M / BM, 1), 256>>>(
        xn, qkv_w, qkv_b, nullptr, qkv,
        M, 3072, 1024, 1024, 3072, 3072,
        0, 0, 0, 0, 0, 0, 1);

    // 3. Scores: per (b,h): q[2048,512] @ k[2048,512]^T -> scores[2048,2048]
    //    q at col h*512, k at col 1024 + h*512 within the 3072-wide qkv rows.
    gemm_k<1, EPI_NONE><<<dim3(2048 / BN, 2048 / BM, 16), 256>>>(
        qkv, qkv + 1024, nullptr, nullptr, scores,
        2048, 2048, 512, 3072, 3072, 2048,
        2048LL * 3072, 512,      // A (q): per-b, per-h
        2048LL * 3072, 512,      // B (k)
        2 * X, X,                // C (scores): z = b*2+h
        2);

    // 4. Softmax(scale * scores), in place. scale = 1/sqrt(512)
    softmax_k<<<16 * 2048, 256>>>(scores, 2048, 0.04419417382415922f);

    // 5. AV: per (b,h): scores[2048,2048] @ v[2048,512] -> attnout cols h*512..
    gemm_k<0, EPI_NONE><<<dim3(512 / BN, 2048 / BM, 16), 256>>>(
        scores, qkv + 2048, nullptr, nullptr, attnout,
        2048, 512, 2048, 2048, 3072, 1024,
        2 * X, X,                // A (scores)
        2048LL * 3072, 512,      // B (v)
        2048LL * 1024, 512,      // C (attnout)
        2);

    // 6. Proj + residual: attnout @ proj_w + proj_b + x -> x1
    gemm_k<0, EPI_BIAS_RES><<<dim3(1024 / BN, M / BM, 1), 256>>>(
        attnout, proj_w, proj_b, x, x1,
        M, 1024, 1024, 1024, 1024, 1024,
        0, 0, 0, 0, 0, 0, 1);

    // 7. LN2: x1 -> xn (reuse)
    ln_k<<<M, 256>>>(x1, ln2_w, ln2_b, xn, 1024);

    // 8. MLP1 + exact GELU: xn @ mlp_w1 + mlp_b1 -> hdn
    gemm_k<0, EPI_BIAS_GELU><<<dim3(2048 / BN, M / BM, 1), 256>>>(
        xn, mlp_w1, mlp_b1, nullptr, hdn,
        M, 2048, 1024, 1024, 2048, 2048,
        0, 0, 0, 0, 0, 0, 1);

    // 9. MLP2 + residual: hdn @ mlp_w2 + mlp_b2 + x1 -> out
    gemm_k<0, EPI_BIAS_RES><<<dim3(1024 / BN, M / BM, 1), 256>>>(
        hdn, mlp_w2, mlp_b2, x1, out,
        M, 1024, 2048, 2048, 1024, 1024,
        0, 0, 0, 0, 0, 0, 1);
}

// round 2
// speedup vs baseline: 2.5082x; 2.5082x over previous
#include <cuda_runtime.h>
#include <math.h>

// ---------------------------------------------------------------------------
// B=8, N=2048, C=1024, heads=2, d=512, H=2048.  M = B*N = 16384.
// GEMMs on tensor cores via mma.sync m16n8k8 tf32 (fp32 accumulate).
// ---------------------------------------------------------------------------

#define BM 128
#define BN 128
#define BKT 16   // k-tile for tensor-core gemm

enum { EPI_NONE = 0, EPI_BIAS = 1, EPI_BIAS_RES = 2, EPI_BIAS_GELU = 3 };

// Scratch (device globals; allocation-free per harness rules). ~768 MB total.
__device__ float g_xn[16384 * 1024];
__device__ float g_qkv[16384 * 3072];
__device__ float g_scores[16ull * 2048 * 2048];
__device__ float g_attnout[16384 * 1024];
__device__ float g_x1[16384 * 1024];
__device__ float g_hdn[16384 * 2048];

__device__ __forceinline__ unsigned f2tf32(float x) {
    unsigned r;
    asm("cvt.rna.tf32.f32 %0, %1;" : "=r"(r) : "f"(x));
    return r;
}

__device__ __forceinline__ void mma_tf32(float c[4], const unsigned a[4], const unsigned b[2]) {
    asm volatile(
        "mma.sync.aligned.m16n8k8.row.col.f32.tf32.tf32.f32 "
        "{%0,%1,%2,%3}, {%4,%5,%6,%7}, {%8,%9}, {%0,%1,%2,%3};"
        : "+f"(c[0]), "+f"(c[1]), "+f"(c[2]), "+f"(c[3])
        : "r"(a[0]), "r"(a[1]), "r"(a[2]), "r"(a[3]), "r"(b[0]), "r"(b[1]));
}

// ---------------------------------------------------------------------------
// Tensor-core SGEMM (tf32): C[z] = A[z] @ B[z] (+bias)(+resid)(gelu)
// TB=1 -> B is [N,K] row-major (compute A @ B^T).
// M,N multiples of 128; K multiple of 16.
// ---------------------------------------------------------------------------
template <int TB, int EPI>
__global__ __launch_bounds__(256, 2) void gemm_tc(
    const float* __restrict__ A, const float* __restrict__ B,
    const float* __restrict__ bias, const float* __restrict__ resid,
    float* __restrict__ C,
    int M, int N, int K, int lda, int ldb, int ldc,
    long long soA, long long siA,
    long long soB, long long siB,
    long long soC, long long siC, int ic)
{
    // pad 8 -> conflict-free fragment loads (row stride 136: 8-bank shift per k-row)
    __shared__ __align__(16) unsigned As[2][BKT][BM + 8];
    __shared__ __align__(16) unsigned Bs[2][BKT][BN + 8];

    const int z = blockIdx.z;
    A += (long long)(z / ic) * soA + (long long)(z % ic) * siA;
    B += (long long)(z / ic) * soB + (long long)(z % ic) * siB;
    C += (long long)(z / ic) * soC + (long long)(z % ic) * siC;

    const int m0 = blockIdx.y * BM;
    const int n0 = blockIdx.x * BN;
    const int tid = threadIdx.x;
    const int lane = tid & 31;
    const int warp = tid >> 5;
    const int wm = (warp & 1) * 64;   // warp row offset
    const int wn = (warp >> 1) * 32;  // warp col offset
    const int lq = lane >> 2;         // 0..7
    const int lr = lane & 3;          // 0..3

    float acc[4][4][4];
#pragma unroll
    for (int i = 0; i < 4; i++)
#pragma unroll
        for (int j = 0; j < 4; j++)
#pragma unroll
            for (int c = 0; c < 4; c++) acc[i][j][c] = 0.0f;

    auto load_tile = [&](int k0, int p) {
        // A tile: 128 rows x 16 cols -> As[k][m]
#pragma unroll
        for (int t = 0; t < 2; t++) {
            int idx = tid + t * 256;
            int r = idx >> 2, c4 = (idx & 3) * 4;
            float4 av = *(const float4*)(A + (size_t)(m0 + r) * lda + k0 + c4);
            As[p][c4 + 0][r] = f2tf32(av.x);
            As[p][c4 + 1][r] = f2tf32(av.y);
            As[p][c4 + 2][r] = f2tf32(av.z);
            As[p][c4 + 3][r] = f2tf32(av.w);
        }
        if (TB) {
            // B[n,k] row-major: 128 n-rows x 16 k-cols -> Bs[k][n]
#pragma unroll
            for (int t = 0; t < 2; t++) {
                int idx = tid + t * 256;
                int r = idx >> 2, c4 = (idx & 3) * 4;
                float4 bv = *(const float4*)(B + (size_t)(n0 + r) * ldb + k0 + c4);
                Bs[p][c4 + 0][r] = f2tf32(bv.x);
                Bs[p][c4 + 1][r] = f2tf32(bv.y);
                Bs[p][c4 + 2][r] = f2tf32(bv.z);
                Bs[p][c4 + 3][r] = f2tf32(bv.w);
            }
        } else {
            // B[k,n] row-major: 16 k-rows x 128 n-cols -> Bs[k][n]
#pragma unroll
            for (int t = 0; t < 2; t++) {
                int idx = tid + t * 256;
                int r = idx >> 5, c4 = (idx & 31) * 4;
                float4 bv = *(const float4*)(B + (size_t)(k0 + r) * ldb + n0 + c4);
                uint4 u;
                u.x = f2tf32(bv.x); u.y = f2tf32(bv.y);
                u.z = f2tf32(bv.z); u.w = f2tf32(bv.w);
                *(uint4*)&Bs[p][r][c4] = u;
            }
        }
    };

    load_tile(0, 0);
    __syncthreads();

    int p = 0;
    for (int k0 = 0; k0 < K; k0 += BKT) {
        if (k0 + BKT < K) load_tile(k0 + BKT, p ^ 1);

#pragma unroll
        for (int kk = 0; kk < BKT; kk += 8) {
            unsigned a[4][4], b[4][2];
#pragma unroll
            for (int mi = 0; mi < 4; mi++) {
                const int rb = wm + mi * 16 + lq;
                a[mi][0] = As[p][kk + lr][rb];
                a[mi][1] = As[p][kk + lr][rb + 8];
                a[mi][2] = As[p][kk + lr + 4][rb];
                a[mi][3] = As[p][kk + lr + 4][rb + 8];
            }
#pragma unroll
            for (int ni = 0; ni < 4; ni++) {
                const int cb = wn + ni * 8 + lq;
                b[ni][0] = Bs[p][kk + lr][cb];
                b[ni][1] = Bs[p][kk + lr + 4][cb];
            }
#pragma unroll
            for (int mi = 0; mi < 4; mi++)
#pragma unroll
                for (int ni = 0; ni < 4; ni++)
                    mma_tf32(acc[mi][ni], a[mi], b[ni]);
        }
        __syncthreads();
        p ^= 1;
    }

    // Epilogue
#pragma unroll
    for (int mi = 0; mi < 4; mi++) {
#pragma unroll
        for (int ni = 0; ni < 4; ni++) {
            const int row = m0 + wm + mi * 16 + lq;
            const int col = n0 + wn + ni * 8 + lr * 2;
#pragma unroll
            for (int h = 0; h < 2; h++) {
                const int r = row + h * 8;
                float v0 = acc[mi][ni][h * 2 + 0];
                float v1 = acc[mi][ni][h * 2 + 1];
                if (EPI != EPI_NONE) { v0 += bias[col]; v1 += bias[col + 1]; }
                if (EPI == EPI_BIAS_RES) {
                    v0 += resid[(size_t)r * ldc + col];
                    v1 += resid[(size_t)r * ldc + col + 1];
                }
                if (EPI == EPI_BIAS_GELU) {
                    v0 = 0.5f * v0 * (1.0f + erff(v0 * 0.70710678118654752f));
                    v1 = 0.5f * v1 * (1.0f + erff(v1 * 0.70710678118654752f));
                }
                float2 o; o.x = v0; o.y = v1;
                *(float2*)(C + (size_t)r * ldc + col) = o;
            }
        }
    }
}

// ---------------------------------------------------------------------------
// LayerNorm: one block per row of C=1024
// ---------------------------------------------------------------------------
__global__ __launch_bounds__(256) void ln_k(
    const float* __restrict__ x, const float* __restrict__ w,
    const float* __restrict__ b, float* __restrict__ out, int C)
{
    const size_t row = blockIdx.x;
    const float* xr = x + row * C;
    float sum = 0.0f, sq = 0.0f;
    for (int i = threadIdx.x; i < C; i += blockDim.x) {
        float v = xr[i];
        sum += v;
        sq += v * v;
    }
    __shared__ float s1[32], s2[32];
#pragma unroll
    for (int o = 16; o; o >>= 1) {
        sum += __shfl_xor_sync(0xffffffffu, sum, o);
        sq  += __shfl_xor_sync(0xffffffffu, sq, o);
    }
    const int wid = threadIdx.x >> 5, lid = threadIdx.x & 31;
    if (!lid) { s1[wid] = sum; s2[wid] = sq; }
    __syncthreads();
    if (threadIdx.x < 32) {
        const int nw = blockDim.x >> 5;
        float v1 = (threadIdx.x < nw) ? s1[threadIdx.x] : 0.0f;
        float v2 = (threadIdx.x < nw) ? s2[threadIdx.x] : 0.0f;
#pragma unroll
        for (int o = 16; o; o >>= 1) {
            v1 += __shfl_xor_sync(0xffffffffu, v1, o);
            v2 += __shfl_xor_sync(0xffffffffu, v2, o);
        }
        if (!threadIdx.x) { s1[0] = v1; s2[0] = v2; }
    }
    __syncthreads();
    const float mu = s1[0] / (float)C;
    const float var = s2[0] / (float)C - mu * mu;
    const float rstd = rsqrtf(var + 1e-5f);
    float* orow = out + row * C;
    for (int i = threadIdx.x; i < C; i += blockDim.x)
        orow[i] = (xr[i] - mu) * rstd * w[i] + b[i];
}

// ---------------------------------------------------------------------------
// In-place scaled softmax over rows of length n: softmax(scale * s)
// ---------------------------------------------------------------------------
__global__ __launch_bounds__(256) void softmax_k(float* __restrict__ s, int n, float scale)
{
    float* row = s + (size_t)blockIdx.x * n;
    __shared__ float red[32];
    const int wid = threadIdx.x >> 5, lid = threadIdx.x & 31;
    const int nw = blockDim.x >> 5;

    float mx = -3.4e38f;
    for (int i = threadIdx.x; i < n; i += blockDim.x) mx = fmaxf(mx, row[i]);
#pragma unroll
    for (int o = 16; o; o >>= 1) mx = fmaxf(mx, __shfl_xor_sync(0xffffffffu, mx, o));
    if (!lid) red[wid] = mx;
    __syncthreads();
    if (threadIdx.x < 32) {
        float v = (threadIdx.x < nw) ? red[threadIdx.x] : -3.4e38f;
#pragma unroll
        for (int o = 16; o; o >>= 1) v = fmaxf(v, __shfl_xor_sync(0xffffffffu, v, o));
        if (!threadIdx.x) red[0] = v;
    }
    __syncthreads();
    mx = red[0];
    __syncthreads();

    float sum = 0.0f;
    for (int i = threadIdx.x; i < n; i += blockDim.x) {
        float e = expf(scale * (row[i] - mx));
        row[i] = e;
        sum += e;
    }
#pragma unroll
    for (int o = 16; o; o >>= 1) sum += __shfl_xor_sync(0xffffffffu, sum, o);
    if (!lid) red[wid] = sum;
    __syncthreads();
    if (threadIdx.x < 32) {
        float v = (threadIdx.x < nw) ? red[threadIdx.x] : 0.0f;
#pragma unroll
        for (int o = 16; o; o >>= 1) v += __shfl_xor_sync(0xffffffffu, v, o);
        if (!threadIdx.x) red[0] = v;
    }
    __syncthreads();
    const float inv = 1.0f / red[0];
    for (int i = threadIdx.x; i < n; i += blockDim.x) row[i] *= inv;
}

// ---------------------------------------------------------------------------
// Inputs: x, ln1_w, ln1_b, qkv_w, qkv_b, proj_w, proj_b, ln2_w, ln2_b,
//         mlp_w1, mlp_b1, mlp_w2, mlp_b2
// ---------------------------------------------------------------------------
extern "C" void kernel_launch(void* const* d_in, const int* in_sizes, int n_in,
                              void* d_out, int out_size)
{
    const float* x      = (const float*)d_in[0];
    const float* ln1_w  = (const float*)d_in[1];
    const float* ln1_b  = (const float*)d_in[2];
    const float* qkv_w  = (const float*)d_in[3];
    const float* qkv_b  = (const float*)d_in[4];
    const float* proj_w = (const float*)d_in[5];
    const float* proj_b = (const float*)d_in[6];
    const float* ln2_w  = (const float*)d_in[7];
    const float* ln2_b  = (const float*)d_in[8];
    const float* mlp_w1 = (const float*)d_in[9];
    const float* mlp_b1 = (const float*)d_in[10];
    const float* mlp_w2 = (const float*)d_in[11];
    const float* mlp_b2 = (const float*)d_in[12];
    float* out = (float*)d_out;

    void *p_xn, *p_qkv, *p_sc, *p_ao, *p_x1, *p_hd;
    cudaGetSymbolAddress(&p_xn,  g_xn);
    cudaGetSymbolAddress(&p_qkv, g_qkv);
    cudaGetSymbolAddress(&p_sc,  g_scores);
    cudaGetSymbolAddress(&p_ao,  g_attnout);
    cudaGetSymbolAddress(&p_x1,  g_x1);
    cudaGetSymbolAddress(&p_hd,  g_hdn);
    float* xn      = (float*)p_xn;
    float* qkv     = (float*)p_qkv;
    float* scores  = (float*)p_sc;
    float* attnout = (float*)p_ao;
    float* x1      = (float*)p_x1;
    float* hdn     = (float*)p_hd;

    const int M = 16384;
    const long long X = 2048LL * 2048LL;

    // 1. LN1
    ln_k<<<M, 256>>>(x, ln1_w, ln1_b, xn, 1024);

    // 2. QKV GEMM
    gemm_tc<0, EPI_BIAS><<<dim3(3072 / BN, M / BM, 1), 256>>>(
        xn, qkv_w, qkv_b, nullptr, qkv,
        M, 3072, 1024, 1024, 3072, 3072,
        0, 0, 0, 0, 0, 0, 1);

    // 3. Scores: q @ k^T per (b,h)
    gemm_tc<1, EPI_NONE><<<dim3(2048 / BN, 2048 / BM, 16), 256>>>(
        qkv, qkv + 1024, nullptr, nullptr, scores,
        2048, 2048, 512, 3072, 3072, 2048,
        2048LL * 3072, 512,
        2048LL * 3072, 512,
        2 * X, X,
        2);

    // 4. Softmax(scale * scores)
    softmax_k<<<16 * 2048, 256>>>(scores, 2048, 0.04419417382415922f);

    // 5. AV per (b,h)
    gemm_tc<0, EPI_NONE><<<dim3(512 / BN, 2048 / BM, 16), 256>>>(
        scores, qkv + 2048, nullptr, nullptr, attnout,
        2048, 512, 2048, 2048, 3072, 1024,
        2 * X, X,
        2048LL * 3072, 512,
        2048LL * 1024, 512,
        2);

    // 6. Proj + residual
    gemm_tc<0, EPI_BIAS_RES><<<dim3(1024 / BN, M / BM, 1), 256>>>(
        attnout, proj_w, proj_b, x, x1,
        M, 1024, 1024, 1024, 1024, 1024,
        0, 0, 0, 0, 0, 0, 1);

    // 7. LN2
    ln_k<<<M, 256>>>(x1, ln2_w, ln2_b, xn, 1024);

    // 8. MLP1 + exact GELU
    gemm_tc<0, EPI_BIAS_GELU><<<dim3(2048 / BN, M / BM, 1), 256>>>(
        xn, mlp_w1, mlp_b1, nullptr, hdn,
        M, 2048, 1024, 1024, 2048, 2048,
        0, 0, 0, 0, 0, 0, 1);

    // 9. MLP2 + residual -> out
    gemm_tc<0, EPI_BIAS_RES><<<dim3(1024 / BN, M / BM, 1), 256>>>(
        hdn, mlp_w2, mlp_b2, x1, out,
        M, 1024, 2048, 2048, 1024, 1024,
        0, 0, 0, 0, 0, 0, 1);
}

// round 3
// speedup vs baseline: 5.9060x; 2.3547x over previous
#include <cuda_runtime.h>
#include <cuda_fp16.h>
#include <math.h>

// ---------------------------------------------------------------------------
// B=8, N=2048, C=1024, heads=2, d=512, H=2048.  M = B*N = 16384.
// All GEMMs: fp16 inputs (A[m][k], B[n][k] both k-contiguous), fp32 accum,
// mma.sync m16n8k16, cp.async 3-stage pipeline, conflict-free padded smem.
// ---------------------------------------------------------------------------

#define BM 128
#define BN 128
#define BK 32
#define ASTR 40        // padded smem row stride in halfs (80B) -> conflict-free
#define STG_HALFS (2 * 128 * ASTR)   // A + B per stage
#define SMEM_BYTES (3 * STG_HALFS * 2)

enum { EPI_NONE = 0, EPI_BIAS = 1, EPI_BIAS_RES = 2, EPI_BIAS_GELU = 3 };

// ---------------- scratch (device globals, allocation-free) ----------------
__device__ __half g_xn[16384 * 1024];
__device__ __half g_qkv[16384 * 3072];
__device__ __half g_vT[16ull * 512 * 2048];
__device__ __half g_scores[16ull * 2048 * 2048];
__device__ __half g_attnout[16384 * 1024];
__device__ float  g_x1[16384 * 1024];
__device__ __half g_hdn[16384 * 2048];
__device__ __half g_qkvwT[3072 * 1024];
__device__ __half g_projwT[1024 * 1024];
__device__ __half g_w1T[2048 * 1024];
__device__ __half g_w2T[1024 * 2048];

__device__ __forceinline__ void cpa16(__half* dst, const __half* src) {
    unsigned d = (unsigned)__cvta_generic_to_shared(dst);
    asm volatile("cp.async.cg.shared.global [%0], [%1], 16;" :: "r"(d), "l"(src));
}

__device__ __forceinline__ void mma_f16(float c[4], const unsigned a[4], const unsigned b[2]) {
    asm volatile(
        "mma.sync.aligned.m16n8k16.row.col.f32.f16.f16.f32 "
        "{%0,%1,%2,%3}, {%4,%5,%6,%7}, {%8,%9}, {%0,%1,%2,%3};"
        : "+f"(c[0]), "+f"(c[1]), "+f"(c[2]), "+f"(c[3])
        : "r"(a[0]), "r"(a[1]), "r"(a[2]), "r"(a[3]), "r"(b[0]), "r"(b[1]));
}

// ---------------------------------------------------------------------------
// fp16 tensor-core GEMM: C[z] = A[z] @ B[z]^T (+bias)(+resid)(gelu)
// A: [M][K] ld=lda, B: [N][K] ld=ldb (k-contiguous). K % 32 == 0, K/32 >= 3.
// ---------------------------------------------------------------------------
template <int EPI, typename OutT>
__global__ __launch_bounds__(256, 2) void gemm_h(
    const __half* __restrict__ A, const __half* __restrict__ B,
    const float* __restrict__ bias, const float* __restrict__ resid,
    OutT* __restrict__ C,
    int K, int lda, int ldb, int ldc,
    long long soA, long long siA,
    long long soB, long long siB,
    long long soC, long long siC, int ic)
{
    extern __shared__ __half smem[];

    const int z = blockIdx.z;
    A += (long long)(z / ic) * soA + (long long)(z % ic) * siA;
    B += (long long)(z / ic) * soB + (long long)(z % ic) * siB;
    C += (long long)(z / ic) * soC + (long long)(z % ic) * siC;

    const int m0 = blockIdx.y * BM;
    const int n0 = blockIdx.x * BN;
    const int tid = threadIdx.x;
    const int lane = tid & 31;
    const int warp = tid >> 5;
    const int wm = (warp & 1) * 64;
    const int wn = (warp >> 1) * 32;
    const int lq = lane >> 2;   // groupID 0..7
    const int lr = lane & 3;    // tig 0..3

    float acc[4][4][4];
#pragma unroll
    for (int i = 0; i < 4; i++)
#pragma unroll
        for (int j = 0; j < 4; j++)
#pragma unroll
            for (int c = 0; c < 4; c++) acc[i][j][c] = 0.0f;

    const int ldr = tid >> 2;        // 0..63  (two passes -> 128 rows)
    const int ldc4 = (tid & 3) * 8;  // 16B chunk within 32-half row

    auto load_tile = [&](int t, int s) {
        __half* sA = smem + s * STG_HALFS;
        __half* sB = sA + 128 * ASTR;
        const __half* gA = A + (size_t)(m0 + ldr) * lda + t * BK + ldc4;
        const __half* gB = B + (size_t)(n0 + ldr) * ldb + t * BK + ldc4;
        cpa16(sA + ldr * ASTR + ldc4, gA);
        cpa16(sA + (ldr + 64) * ASTR + ldc4, gA + (size_t)64 * lda);
        cpa16(sB + ldr * ASTR + ldc4, gB);
        cpa16(sB + (ldr + 64) * ASTR + ldc4, gB + (size_t)64 * ldb);
    };

    const int ntiles = K / BK;
    load_tile(0, 0);
    asm volatile("cp.async.commit_group;");
    load_tile(1, 1);
    asm volatile("cp.async.commit_group;");

    int p = 0;
    for (int t = 0; t < ntiles; t++) {
        asm volatile("cp.async.wait_group 1;");
        __syncthreads();

        const __half* sA = smem + p * STG_HALFS;
        const __half* sB = sA + 128 * ASTR;
#pragma unroll
        for (int kk = 0; kk < BK; kk += 16) {
            unsigned a[4][4], b[4][2];
#pragma unroll
            for (int mi = 0; mi < 4; mi++) {
                const __half* pa = sA + (wm + mi * 16 + lq) * ASTR + kk + lr * 2;
                a[mi][0] = *(const unsigned*)pa;
                a[mi][1] = *(const unsigned*)(pa + 8 * ASTR);
                a[mi][2] = *(const unsigned*)(pa + 8);
                a[mi][3] = *(const unsigned*)(pa + 8 * ASTR + 8);
            }
#pragma unroll
            for (int ni = 0; ni < 4; ni++) {
                const __half* pb = sB + (wn + ni * 8 + lq) * ASTR + kk + lr * 2;
                b[ni][0] = *(const unsigned*)pb;
                b[ni][1] = *(const unsigned*)(pb + 8);
            }
#pragma unroll
            for (int mi = 0; mi < 4; mi++)
#pragma unroll
                for (int ni = 0; ni < 4; ni++)
                    mma_f16(acc[mi][ni], a[mi], b[ni]);
        }
        __syncthreads();
        if (t + 2 < ntiles) load_tile(t + 2, (p + 2) % 3);
        asm volatile("cp.async.commit_group;");
        p = (p + 1) % 3;
    }

    // Epilogue
#pragma unroll
    for (int mi = 0; mi < 4; mi++) {
#pragma unroll
        for (int ni = 0; ni < 4; ni++) {
            const int row = m0 + wm + mi * 16 + lq;
            const int col = n0 + wn + ni * 8 + lr * 2;
            float bx = 0.f, by = 0.f;
            if (EPI != EPI_NONE) { bx = bias[col]; by = bias[col + 1]; }
#pragma unroll
            for (int h = 0; h < 2; h++) {
                const int r = row + h * 8;
                float v0 = acc[mi][ni][h * 2 + 0] + bx;
                float v1 = acc[mi][ni][h * 2 + 1] + by;
                if (EPI == EPI_BIAS_RES) {
                    v0 += resid[(size_t)r * ldc + col];
                    v1 += resid[(size_t)r * ldc + col + 1];
                }
                if (EPI == EPI_BIAS_GELU) {
                    v0 = 0.5f * v0 * (1.0f + erff(v0 * 0.70710678118654752f));
                    v1 = 0.5f * v1 * (1.0f + erff(v1 * 0.70710678118654752f));
                }
                if constexpr (sizeof(OutT) == 2) {
                    __half2 o = __floats2half2_rn(v0, v1);
                    *(__half2*)((__half*)C + (size_t)r * ldc + col) = o;
                } else {
                    float2 o; o.x = v0; o.y = v1;
                    *(float2*)((float*)C + (size_t)r * ldc + col) = o;
                }
            }
        }
    }
}

// ---------------------------------------------------------------------------
// LayerNorm (C=1024 hardcoded): fp32 in -> fp16 out. One block per row.
// ---------------------------------------------------------------------------
__global__ __launch_bounds__(256) void ln_k(
    const float* __restrict__ x, const float* __restrict__ w,
    const float* __restrict__ b, __half* __restrict__ out)
{
    const size_t row = blockIdx.x;
    const int tid = threadIdx.x;
    float4 v = ((const float4*)(x + row * 1024))[tid];
    float sum = v.x + v.y + v.z + v.w;
    float sq = v.x * v.x + v.y * v.y + v.z * v.z + v.w * v.w;

    __shared__ float s1[8], s2[8];
#pragma unroll
    for (int o = 16; o; o >>= 1) {
        sum += __shfl_xor_sync(0xffffffffu, sum, o);
        sq  += __shfl_xor_sync(0xffffffffu, sq, o);
    }
    const int wid = tid >> 5, lid = tid & 31;
    if (!lid) { s1[wid] = sum; s2[wid] = sq; }
    __syncthreads();
    if (tid < 32) {
        float v1 = (tid < 8) ? s1[tid] : 0.0f;
        float v2 = (tid < 8) ? s2[tid] : 0.0f;
#pragma unroll
        for (int o = 4; o; o >>= 1) {
            v1 += __shfl_xor_sync(0xffffffffu, v1, o);
            v2 += __shfl_xor_sync(0xffffffffu, v2, o);
        }
        if (!tid) { s1[0] = v1; s2[0] = v2; }
    }
    __syncthreads();
    const float mu = s1[0] * (1.0f / 1024.0f);
    const float var = s2[0] * (1.0f / 1024.0f) - mu * mu;
    const float rstd = rsqrtf(var + 1e-5f);

    float4 w4 = ((const float4*)w)[tid];
    float4 b4 = ((const float4*)b)[tid];
    float o0 = (v.x - mu) * rstd * w4.x + b4.x;
    float o1 = (v.y - mu) * rstd * w4.y + b4.y;
    float o2 = (v.z - mu) * rstd * w4.z + b4.z;
    float o3 = (v.w - mu) * rstd * w4.w + b4.w;
    __half2* op = (__half2*)(out + row * 1024);
    op[tid * 2 + 0] = __floats2half2_rn(o0, o1);
    op[tid * 2 + 1] = __floats2half2_rn(o2, o3);
}

// ---------------------------------------------------------------------------
// Softmax over fp16 rows of length 2048: softmax(scale * s), in place.
// ---------------------------------------------------------------------------
__global__ __launch_bounds__(256) void softmax_h(__half* __restrict__ s, float scale)
{
    __half2* row = (__half2*)(s + (size_t)blockIdx.x * 2048);  // 1024 half2
    const int tid = threadIdx.x;
    __shared__ float red[8];
    const int wid = tid >> 5, lid = tid & 31;

    float mx = -3.4e38f;
    float2 vals[4][1];
#pragma unroll
    for (int k = 0; k < 4; k++) {
        float2 f = __half22float2(row[tid + k * 256]);
        mx = fmaxf(mx, fmaxf(f.x, f.y));
    }
#pragma unroll
    for (int o = 16; o; o >>= 1) mx = fmaxf(mx, __shfl_xor_sync(0xffffffffu, mx, o));
    if (!lid) red[wid] = mx;
    __syncthreads();
    if (tid < 32) {
        float v = (tid < 8) ? red[tid] : -3.4e38f;
#pragma unroll
        for (int o = 4; o; o >>= 1) v = fmaxf(v, __shfl_xor_sync(0xffffffffu, v, o));
        if (!tid) red[0] = v;
    }
    __syncthreads();
    mx = red[0];
    __syncthreads();

    float sum = 0.0f;
#pragma unroll
    for (int k = 0; k < 4; k++) {
        float2 f = __half22float2(row[tid + k * 256]);
        float e0 = expf(scale * (f.x - mx));
        float e1 = expf(scale * (f.y - mx));
        vals[k][0].x = e0; vals[k][0].y = e1;
        sum += e0 + e1;
    }
#pragma unroll
    for (int o = 16; o; o >>= 1) sum += __shfl_xor_sync(0xffffffffu, sum, o);
    if (!lid) red[wid] = sum;
    __syncthreads();
    if (tid < 32) {
        float v = (tid < 8) ? red[tid] : 0.0f;
#pragma unroll
        for (int o = 4; o; o >>= 1) v += __shfl_xor_sync(0xffffffffu, v, o);
        if (!tid) red[0] = v;
    }
    __syncthreads();
    const float inv = 1.0f / red[0];
#pragma unroll
    for (int k = 0; k < 4; k++)
        row[tid + k * 256] = __floats2half2_rn(vals[k][0].x * inv, vals[k][0].y * inv);
}

// ---------------------------------------------------------------------------
// Weight transpose + fp32->fp16: in [R][C] -> out [C][R]. Block 32x8.
// ---------------------------------------------------------------------------
__global__ void wtrans_k(const float* __restrict__ in, __half* __restrict__ out,
                         int R, int C)
{
    __shared__ __half t[32][33];
    const int c0 = blockIdx.x * 32, r0 = blockIdx.y * 32;
    const int x = threadIdx.x, y = threadIdx.y;
#pragma unroll
    for (int j = 0; j < 4; j++)
        t[y + j * 8][x] = __float2half_rn(in[(size_t)(r0 + y + j * 8) * C + c0 + x]);
    __syncthreads();
#pragma unroll
    for (int j = 0; j < 4; j++)
        out[(size_t)(c0 + y + j * 8) * R + r0 + x] = t[x][y + j * 8];
}

// ---------------------------------------------------------------------------
// V transpose (fp16): per z=(b,h): qkv[b, :, 2048+h*512 .. +512] (2048x512,
// ld 3072) -> vT[z] (512x2048). Block 32x8.
// ---------------------------------------------------------------------------
__global__ void vtrans_k(const __half* __restrict__ qkv, __half* __restrict__ vT)
{
    __shared__ __half t[32][33];
    const int z = blockIdx.z;
    const __half* in = qkv + (size_t)(z >> 1) * 2048 * 3072 + 2048 + (z & 1) * 512;
    __half* out = vT + (size_t)z * 512 * 2048;
    const int c0 = blockIdx.x * 32, r0 = blockIdx.y * 32;
    const int x = threadIdx.x, y = threadIdx.y;
#pragma unroll
    for (int j = 0; j < 4; j++)
        t[y + j * 8][x] = in[(size_t)(r0 + y + j * 8) * 3072 + c0 + x];
    __syncthreads();
#pragma unroll
    for (int j = 0; j < 4; j++)
        out[(size_t)(c0 + y + j * 8) * 2048 + r0 + x] = t[x][y + j * 8];
}

// ---------------------------------------------------------------------------
extern "C" void kernel_launch(void* const* d_in, const int* in_sizes, int n_in,
                              void* d_out, int out_size)
{
    const float* x      = (const float*)d_in[0];
    const float* ln1_w  = (const float*)d_in[1];
    const float* ln1_b  = (const float*)d_in[2];
    const float* qkv_w  = (const float*)d_in[3];
    const float* qkv_b  = (const float*)d_in[4];
    const float* proj_w = (const float*)d_in[5];
    const float* proj_b = (const float*)d_in[6];
    const float* ln2_w  = (const float*)d_in[7];
    const float* ln2_b  = (const float*)d_in[8];
    const float* mlp_w1 = (const float*)d_in[9];
    const float* mlp_b1 = (const float*)d_in[10];
    const float* mlp_w2 = (const float*)d_in[11];
    const float* mlp_b2 = (const float*)d_in[12];
    float* out = (float*)d_out;

    void *p;
    cudaGetSymbolAddress(&p, g_xn);      __half* xn      = (__half*)p;
    cudaGetSymbolAddress(&p, g_qkv);     __half* qkv     = (__half*)p;
    cudaGetSymbolAddress(&p, g_vT);      __half* vT      = (__half*)p;
    cudaGetSymbolAddress(&p, g_scores);  __half* scores  = (__half*)p;
    cudaGetSymbolAddress(&p, g_attnout); __half* attnout = (__half*)p;
    cudaGetSymbolAddress(&p, g_x1);      float*  x1      = (float*)p;
    cudaGetSymbolAddress(&p, g_hdn);     __half* hdn     = (__half*)p;
    cudaGetSymbolAddress(&p, g_qkvwT);   __half* qkvwT   = (__half*)p;
    cudaGetSymbolAddress(&p, g_projwT);  __half* projwT  = (__half*)p;
    cudaGetSymbolAddress(&p, g_w1T);     __half* w1T     = (__half*)p;
    cudaGetSymbolAddress(&p, g_w2T);     __half* w2T     = (__half*)p;

    cudaFuncSetAttribute(gemm_h<EPI_BIAS, __half>,      cudaFuncAttributeMaxDynamicSharedMemorySize, SMEM_BYTES);
    cudaFuncSetAttribute(gemm_h<EPI_NONE, __half>,      cudaFuncAttributeMaxDynamicSharedMemorySize, SMEM_BYTES);
    cudaFuncSetAttribute(gemm_h<EPI_BIAS_RES, float>,   cudaFuncAttributeMaxDynamicSharedMemorySize, SMEM_BYTES);
    cudaFuncSetAttribute(gemm_h<EPI_BIAS_GELU, __half>, cudaFuncAttributeMaxDynamicSharedMemorySize, SMEM_BYTES);

    const int M = 16384;
    const long long X = 2048LL * 2048LL;
    dim3 tb(32, 8);

    // 0. Weight transpose+convert
    wtrans_k<<<dim3(3072 / 32, 1024 / 32), tb>>>(qkv_w,  qkvwT,  1024, 3072);
    wtrans_k<<<dim3(1024 / 32, 1024 / 32), tb>>>(proj_w, projwT, 1024, 1024);
    wtrans_k<<<dim3(2048 / 32, 1024 / 32), tb>>>(mlp_w1, w1T,    1024, 2048);
    wtrans_k<<<dim3(1024 / 32, 2048 / 32), tb>>>(mlp_w2, w2T,    2048, 1024);

    // 1. LN1: x -> xn (fp16)
    ln_k<<<M, 256>>>(x, ln1_w, ln1_b, xn);

    // 2. QKV: xn[16384,1024] @ qkvwT[3072,1024]^T + bias -> qkv (fp16)
    gemm_h<EPI_BIAS, __half><<<dim3(3072 / BN, M / BM, 1), 256, SMEM_BYTES>>>(
        xn, qkvwT, qkv_b, nullptr, qkv,
        1024, 1024, 1024, 3072,
        0, 0, 0, 0, 0, 0, 1);

    // 3. V transpose: qkv -> vT per (b,h)
    vtrans_k<<<dim3(512 / 32, 2048 / 32, 16), tb>>>(qkv, vT);

    // 4. Scores: q @ k^T per (b,h)
    gemm_h<EPI_NONE, __half><<<dim3(2048 / BN, 2048 / BM, 16), 256, SMEM_BYTES>>>(
        qkv, qkv + 1024, nullptr, nullptr, scores,
        512, 3072, 3072, 2048,
        2048LL * 3072, 512,
        2048LL * 3072, 512,
        2 * X, X,
        2);

    // 5. Softmax
    softmax_h<<<16 * 2048, 256>>>(scores, 0.04419417382415922f);

    // 6. AV: probs[2048,2048] @ vT[512,2048]^T -> attnout (fp16)
    gemm_h<EPI_NONE, __half><<<dim3(512 / BN, 2048 / BM, 16), 256, SMEM_BYTES>>>(
        scores, vT, nullptr, nullptr, attnout,
        2048, 2048, 2048, 1024,
        2 * X, X,
        2048LL * 512 * 2, 512LL * 2048,
        2048LL * 1024, 512,
        2);

    // 7. Proj + residual(x) -> x1 (fp32)
    gemm_h<EPI_BIAS_RES, float><<<dim3(1024 / BN, M / BM, 1), 256, SMEM_BYTES>>>(
        attnout, projwT, proj_b, x, x1,
        1024, 1024, 1024, 1024,
        0, 0, 0, 0, 0, 0, 1);

    // 8. LN2: x1 -> xn (fp16)
    ln_k<<<M, 256>>>(x1, ln2_w, ln2_b, xn);

    // 9. MLP1 + GELU -> hdn (fp16)
    gemm_h<EPI_BIAS_GELU, __half><<<dim3(2048 / BN, M / BM, 1), 256, SMEM_BYTES>>>(
        xn, w1T, mlp_b1, nullptr, hdn,
        1024, 1024, 1024, 2048,
        0, 0, 0, 0, 0, 0, 1);

    // 10. MLP2 + residual(x1) -> out (fp32)
    gemm_h<EPI_BIAS_RES, float><<<dim3(1024 / BN, M / BM, 1), 256, SMEM_BYTES>>>(
        hdn, w2T, mlp_b2, x1, out,
        2048, 2048, 2048, 1024,
        0, 0, 0, 0, 0, 0, 1);
}